// round 6
// baseline (speedup 1.0000x reference)
#include <cuda_runtime.h>
#include <math.h>

#define PH 7
#define PW 7
#define C  256
#define C4 (C / 4)
#define MAXN 1024

// Scratch (device globals; no allocation allowed)
__device__ float4 g_sbox[MAXN];   // sorted normalized boxes (y1,x1,y2,x2)
__device__ int    g_slvl[MAXN];   // sorted levels

// ---------------------------------------------------------------------------
// Kernel 1: per-roi level + normalized box, stable counting sort.
// Packed 4x16-bit counters in uint64; warp-shuffle inclusive scan + warp-total
// combine. Single block, 1024 threads, N <= 1024.
// ---------------------------------------------------------------------------
__global__ void level_sort_kernel(const float* __restrict__ rois, int N) {
    __shared__ unsigned long long warp_tot[32];
    int i    = threadIdx.x;
    int lane = i & 31;
    int wid  = i >> 5;

    int lvl = 0;
    float4 nb = make_float4(0.f, 0.f, 0.f, 0.f);
    unsigned long long v = 0ULL;

    if (i < N) {
        float y1 = rois[i * 4 + 0];
        float x1 = rois[i * 4 + 1];
        float y2 = rois[i * 4 + 2];
        float x2 = rois[i * 4 + 3];
        float h = y2 - y1;
        float w = x2 - x1;
        // match reference fp32 path: log(sqrt(h*w))/log(2) - 5, round-half-even
        float lf = logf(sqrtf(h * w)) * (1.0f / logf(2.0f)) - 5.0f;
        int l = (int)rintf(lf);
        l = min(max(l, 0), 3);
        lvl = l;
        const float inv = 1.0f / 1024.0f;
        nb = make_float4(y1 * inv, x1 * inv, y2 * inv, x2 * inv);
        v = 1ULL << (16 * lvl);
    }

    // warp inclusive scan (64-bit)
    unsigned long long incl = v;
#pragma unroll
    for (int off = 1; off < 32; off <<= 1) {
        unsigned long long t = __shfl_up_sync(0xFFFFFFFFu, incl, off);
        if (lane >= off) incl += t;
    }
    if (lane == 31) warp_tot[wid] = incl;
    __syncthreads();

    // warp 0 scans the 32 warp totals (inclusive)
    if (wid == 0) {
        unsigned long long wt = warp_tot[lane];
#pragma unroll
        for (int off = 1; off < 32; off <<= 1) {
            unsigned long long t = __shfl_up_sync(0xFFFFFFFFu, wt, off);
            if (lane >= off) wt += t;
        }
        warp_tot[lane] = wt;
    }
    __syncthreads();

    unsigned long long total = warp_tot[31];
    unsigned long long offset = (wid > 0) ? warp_tot[wid - 1] : 0ULL;
    incl += offset;

    if (i < N) {
        int rank = (int)((incl >> (16 * lvl)) & 0xFFFFULL) - 1;  // exclusive rank in level
        int base = 0;
#pragma unroll
        for (int l = 0; l < 4; l++)
            if (l < lvl) base += (int)((total >> (16 * l)) & 0xFFFFULL);
        int pos = base + rank;
        g_slvl[pos] = lvl;
        g_sbox[pos] = nb;
    }
}

// ---------------------------------------------------------------------------
// Kernel 2: bilinear crop_and_resize gather, one sample point per thread.
// block = (64 channel-groups, 7 px); grid = (N, 7 py).
// Per thread: 4 x LDG.128 + ~15 FFMA + 1 x STG.128. Low regs -> high occupancy
// -> L1 wavefront queue stays fed (the binding resource).
// ---------------------------------------------------------------------------
__global__ void __launch_bounds__(448, 3)
roi_align_kernel(const float* __restrict__ f0,
                 const float* __restrict__ f1,
                 const float* __restrict__ f2,
                 const float* __restrict__ f3,
                 float* __restrict__ out) {
    int roi = blockIdx.x;
    int py  = blockIdx.y;
    int c4  = threadIdx.x;   // 0..63 channel group of 4
    int px  = threadIdx.y;   // 0..6

    float4 b = g_sbox[roi];
    int lvl = g_slvl[roi];

    const float* f = (lvl == 0) ? f0 : (lvl == 1) ? f1 : (lvl == 2) ? f2 : f3;
    int H = 256 >> lvl;
    int W = H;
    float Hm1 = (float)(H - 1);
    float Wm1 = (float)(W - 1);

    float iy = b.x * Hm1 + (float)py * ((b.z - b.x) * Hm1 * (1.0f / (PH - 1)));
    float y0f = floorf(iy);
    float ly = iy - y0f;
    int y0 = min(max((int)y0f, 0), H - 1);
    int y1 = min(max((int)y0f + 1, 0), H - 1);

    float ix = b.y * Wm1 + (float)px * ((b.w - b.y) * Wm1 * (1.0f / (PW - 1)));
    float x0f = floorf(ix);
    float lx = ix - x0f;
    int x0 = min(max((int)x0f, 0), W - 1);
    int x1 = min(max((int)x0f + 1, 0), W - 1);

    bool valid = (iy >= 0.0f) && (iy <= Hm1) && (ix >= 0.0f) && (ix <= Wm1);

    const float4* f4p = (const float4*)f;
    const float4* row0 = f4p + (size_t)y0 * W * C4 + c4;
    const float4* row1 = f4p + (size_t)y1 * W * C4 + c4;

    float4 f00 = __ldg(row0 + x0 * C4);
    float4 f01 = __ldg(row0 + x1 * C4);
    float4 f10 = __ldg(row1 + x0 * C4);
    float4 f11 = __ldg(row1 + x1 * C4);

    float4 r;
    float top, bot;
    top = fmaf(f01.x - f00.x, lx, f00.x);
    bot = fmaf(f11.x - f10.x, lx, f10.x);
    r.x = fmaf(bot - top, ly, top);
    top = fmaf(f01.y - f00.y, lx, f00.y);
    bot = fmaf(f11.y - f10.y, lx, f10.y);
    r.y = fmaf(bot - top, ly, top);
    top = fmaf(f01.z - f00.z, lx, f00.z);
    bot = fmaf(f11.z - f10.z, lx, f10.z);
    r.z = fmaf(bot - top, ly, top);
    top = fmaf(f01.w - f00.w, lx, f00.w);
    bot = fmaf(f11.w - f10.w, lx, f10.w);
    r.w = fmaf(bot - top, ly, top);

    if (!valid) r = make_float4(0.f, 0.f, 0.f, 0.f);

    float4* o = (float4*)out + ((size_t)((roi * PH + py) * PW + px)) * C4 + c4;
    *o = r;
}

extern "C" void kernel_launch(void* const* d_in, const int* in_sizes, int n_in,
                              void* d_out, int out_size) {
    const float* f0   = (const float*)d_in[0];
    const float* f1   = (const float*)d_in[1];
    const float* f2   = (const float*)d_in[2];
    const float* f3   = (const float*)d_in[3];
    const float* rois = (const float*)d_in[4];
    float* out = (float*)d_out;

    int N = in_sizes[4] / 4;
    if (N > MAXN) N = MAXN;

    level_sort_kernel<<<1, 1024>>>(rois, N);

    dim3 grid(N, PH);
    dim3 block(C4, PW);
    roi_align_kernel<<<grid, block>>>(f0, f1, f2, f3, out);
}

// round 7
// speedup vs baseline: 1.0950x; 1.0950x over previous
#include <cuda_runtime.h>
#include <math.h>

#define PH 7
#define PW 7
#define C  256
#define C4 (C / 4)
#define MAXN 1024

// Scratch (device globals; no allocation allowed)
__device__ float4 g_scoord[MAXN];  // per-sorted-roi (ybase, ystep, xbase, xstep) in feature coords
__device__ int    g_slvl[MAXN];    // sorted levels

// ---------------------------------------------------------------------------
// Kernel 1: per-roi level + coordinate bases, stable counting sort.
// Packed 4x16-bit counters in uint64; warp-shuffle inclusive scan + warp-total
// combine. Single block, 1024 threads, N <= 1024.
// ---------------------------------------------------------------------------
__global__ void level_sort_kernel(const float* __restrict__ rois, int N) {
    __shared__ unsigned long long warp_tot[32];
    int i    = threadIdx.x;
    int lane = i & 31;
    int wid  = i >> 5;

    int lvl = 0;
    float4 cb = make_float4(0.f, 0.f, 0.f, 0.f);
    unsigned long long v = 0ULL;

    if (i < N) {
        float y1 = rois[i * 4 + 0];
        float x1 = rois[i * 4 + 1];
        float y2 = rois[i * 4 + 2];
        float x2 = rois[i * 4 + 3];
        float h = y2 - y1;
        float w = x2 - x1;
        // match reference fp32 path: log(sqrt(h*w))/log(2) - 5, round-half-even
        float lf = logf(sqrtf(h * w)) * (1.0f / logf(2.0f)) - 5.0f;
        int l = (int)rintf(lf);
        l = min(max(l, 0), 3);
        lvl = l;
        const float inv = 1.0f / 1024.0f;
        // normalized box (same op order as previously passing kernels)
        float ny1 = y1 * inv, nx1 = x1 * inv, ny2 = y2 * inv, nx2 = x2 * inv;
        float Hm1 = (float)((256 >> l) - 1);
        float Wm1 = Hm1;
        cb.x = ny1 * Hm1;                              // ybase
        cb.y = (ny2 - ny1) * Hm1 * (1.0f / (PH - 1));  // ystep
        cb.z = nx1 * Wm1;                              // xbase
        cb.w = (nx2 - nx1) * Wm1 * (1.0f / (PW - 1));  // xstep
        v = 1ULL << (16 * lvl);
    }

    // warp inclusive scan (64-bit)
    unsigned long long incl = v;
#pragma unroll
    for (int off = 1; off < 32; off <<= 1) {
        unsigned long long t = __shfl_up_sync(0xFFFFFFFFu, incl, off);
        if (lane >= off) incl += t;
    }
    if (lane == 31) warp_tot[wid] = incl;
    __syncthreads();

    if (wid == 0) {
        unsigned long long wt = warp_tot[lane];
#pragma unroll
        for (int off = 1; off < 32; off <<= 1) {
            unsigned long long t = __shfl_up_sync(0xFFFFFFFFu, wt, off);
            if (lane >= off) wt += t;
        }
        warp_tot[lane] = wt;
    }
    __syncthreads();

    unsigned long long total = warp_tot[31];
    unsigned long long offset = (wid > 0) ? warp_tot[wid - 1] : 0ULL;
    incl += offset;

    if (i < N) {
        int rank = (int)((incl >> (16 * lvl)) & 0xFFFFULL) - 1;
        int base = 0;
#pragma unroll
        for (int l = 0; l < 4; l++)
            if (l < lvl) base += (int)((total >> (16 * l)) & 0xFFFFULL);
        int pos = base + rank;
        g_slvl[pos] = lvl;
        g_scoord[pos] = cb;
    }
}

// ---------------------------------------------------------------------------
// Kernel 2: bilinear gather, software-pipelined px loop (depth 2).
// grid = (N, PH); block = 64 (thread = channel-group of 4).
// Loads for px+1 are issued before computing px -> ~8 LDG.128 continuously in
// flight per thread while regs stay ~64 (occupancy ~2x the fully-unrolled
// version). Weight-form bilinear: 4 FMA/channel, 1-deep dependency tree.
// ---------------------------------------------------------------------------
__global__ void __launch_bounds__(64, 12)
roi_align_kernel(const float* __restrict__ f0,
                 const float* __restrict__ f1,
                 const float* __restrict__ f2,
                 const float* __restrict__ f3,
                 float* __restrict__ out) {
    int roi = blockIdx.x;
    int py  = blockIdx.y;
    int c4  = threadIdx.x;   // 0..63

    float4 cb = g_scoord[roi];
    int lvl = g_slvl[roi];

    const float* f = (lvl == 0) ? f0 : (lvl == 1) ? f1 : (lvl == 2) ? f2 : f3;
    int W = 256 >> lvl;
    float Wm1 = (float)(W - 1);
    float Hm1 = Wm1;

    float iy = cb.x + (float)py * cb.y;
    float y0f = floorf(iy);
    float ly = iy - y0f;
    int y0 = min(max((int)y0f, 0), W - 1);
    int y1 = min(max((int)y0f + 1, 0), W - 1);
    bool vy = (iy >= 0.0f) && (iy <= Hm1);
    float omly = 1.0f - ly;

    const float4* f4p = (const float4*)f;
    const float4* row0 = f4p + (size_t)y0 * W * C4 + c4;
    const float4* row1 = f4p + (size_t)y1 * W * C4 + c4;
    float4* o = (float4*)out + ((size_t)(roi * PH + py) * PW) * C4 + c4;

    // prologue: load px = 0
    float lx; bool vx;
    float4 f00, f01, f10, f11;
    {
        float ix = cb.z;
        float x0f = floorf(ix);
        lx = ix - x0f;
        int x0 = min(max((int)x0f, 0), W - 1);
        int x1 = min(max((int)x0f + 1, 0), W - 1);
        vx = (ix >= 0.0f) && (ix <= Wm1);
        f00 = __ldg(row0 + x0 * C4);
        f01 = __ldg(row0 + x1 * C4);
        f10 = __ldg(row1 + x0 * C4);
        f11 = __ldg(row1 + x1 * C4);
    }

#pragma unroll 1
    for (int px = 0; px < PW; px++) {
        // issue next px's loads before computing current
        float nlx = 0.0f; bool nvx = false;
        float4 n00 = f00, n01 = f01, n10 = f10, n11 = f11;
        if (px < PW - 1) {
            float ix = cb.z + (float)(px + 1) * cb.w;
            float x0f = floorf(ix);
            nlx = ix - x0f;
            int x0 = min(max((int)x0f, 0), W - 1);
            int x1 = min(max((int)x0f + 1, 0), W - 1);
            nvx = (ix >= 0.0f) && (ix <= Wm1);
            n00 = __ldg(row0 + x0 * C4);
            n01 = __ldg(row0 + x1 * C4);
            n10 = __ldg(row1 + x0 * C4);
            n11 = __ldg(row1 + x1 * C4);
        }

        // weight-form bilinear on current
        float omlx = 1.0f - lx;
        float w00 = omlx * omly;
        float w01 = lx * omly;
        float w10 = omlx * ly;
        float w11 = lx * ly;

        float4 r;
        r.x = fmaf(f11.x, w11, fmaf(f10.x, w10, fmaf(f01.x, w01, f00.x * w00)));
        r.y = fmaf(f11.y, w11, fmaf(f10.y, w10, fmaf(f01.y, w01, f00.y * w00)));
        r.z = fmaf(f11.z, w11, fmaf(f10.z, w10, fmaf(f01.z, w01, f00.z * w00)));
        r.w = fmaf(f11.w, w11, fmaf(f10.w, w10, fmaf(f01.w, w01, f00.w * w00)));

        if (!(vy && vx)) r = make_float4(0.f, 0.f, 0.f, 0.f);
        o[px * C4] = r;

        // rotate pipeline
        f00 = n00; f01 = n01; f10 = n10; f11 = n11;
        lx = nlx; vx = nvx;
    }
}

extern "C" void kernel_launch(void* const* d_in, const int* in_sizes, int n_in,
                              void* d_out, int out_size) {
    const float* f0   = (const float*)d_in[0];
    const float* f1   = (const float*)d_in[1];
    const float* f2   = (const float*)d_in[2];
    const float* f3   = (const float*)d_in[3];
    const float* rois = (const float*)d_in[4];
    float* out = (float*)d_out;

    int N = in_sizes[4] / 4;
    if (N > MAXN) N = MAXN;

    level_sort_kernel<<<1, 1024>>>(rois, N);

    dim3 grid(N, PH);
    roi_align_kernel<<<grid, 64>>>(f0, f1, f2, f3, out);
}

// round 8
// speedup vs baseline: 1.2284x; 1.1218x over previous
#include <cuda_runtime.h>
#include <math.h>

#define PH 7
#define PW 7
#define C  256
#define C4 (C / 4)
#define MAXN 1024

// Scratch (device globals; no allocation allowed)
__device__ float4 g_scoord[MAXN];  // per-sorted-roi (ybase, ystep, xbase, xstep) in feature coords
__device__ int    g_slvl[MAXN];    // sorted levels

// ---------------------------------------------------------------------------
// Kernel 1: per-roi level + coordinate bases, stable counting sort.
// Packed 4x16-bit counters in uint64; warp-shuffle inclusive scan + warp-total
// combine. Single block, 1024 threads, N <= 1024.
// ---------------------------------------------------------------------------
__global__ void level_sort_kernel(const float* __restrict__ rois, int N) {
    __shared__ unsigned long long warp_tot[32];
    int i    = threadIdx.x;
    int lane = i & 31;
    int wid  = i >> 5;

    int lvl = 0;
    float4 cb = make_float4(0.f, 0.f, 0.f, 0.f);
    unsigned long long v = 0ULL;

    if (i < N) {
        float y1 = rois[i * 4 + 0];
        float x1 = rois[i * 4 + 1];
        float y2 = rois[i * 4 + 2];
        float x2 = rois[i * 4 + 3];
        float h = y2 - y1;
        float w = x2 - x1;
        // match reference fp32 path: log(sqrt(h*w))/log(2) - 5, round-half-even
        float lf = logf(sqrtf(h * w)) * (1.0f / logf(2.0f)) - 5.0f;
        int l = (int)rintf(lf);
        l = min(max(l, 0), 3);
        lvl = l;
        const float inv = 1.0f / 1024.0f;
        float ny1 = y1 * inv, nx1 = x1 * inv, ny2 = y2 * inv, nx2 = x2 * inv;
        float Hm1 = (float)((256 >> l) - 1);
        float Wm1 = Hm1;
        cb.x = ny1 * Hm1;                              // ybase
        cb.y = (ny2 - ny1) * Hm1 * (1.0f / (PH - 1));  // ystep
        cb.z = nx1 * Wm1;                              // xbase
        cb.w = (nx2 - nx1) * Wm1 * (1.0f / (PW - 1));  // xstep
        v = 1ULL << (16 * lvl);
    }

    // warp inclusive scan (64-bit)
    unsigned long long incl = v;
#pragma unroll
    for (int off = 1; off < 32; off <<= 1) {
        unsigned long long t = __shfl_up_sync(0xFFFFFFFFu, incl, off);
        if (lane >= off) incl += t;
    }
    if (lane == 31) warp_tot[wid] = incl;
    __syncthreads();

    if (wid == 0) {
        unsigned long long wt = warp_tot[lane];
#pragma unroll
        for (int off = 1; off < 32; off <<= 1) {
            unsigned long long t = __shfl_up_sync(0xFFFFFFFFu, wt, off);
            if (lane >= off) wt += t;
        }
        warp_tot[lane] = wt;
    }
    __syncthreads();

    unsigned long long total = warp_tot[31];
    unsigned long long offset = (wid > 0) ? warp_tot[wid - 1] : 0ULL;
    incl += offset;

    if (i < N) {
        int rank = (int)((incl >> (16 * lvl)) & 0xFFFFULL) - 1;
        int base = 0;
#pragma unroll
        for (int l = 0; l < 4; l++)
            if (l < lvl) base += (int)((total >> (16 * l)) & 0xFFFFULL);
        int pos = base + rank;
        g_slvl[pos] = lvl;
        g_scoord[pos] = cb;
    }
}

// ---------------------------------------------------------------------------
// Kernel 2: bilinear gather. Full px unroll (max per-thread MLP — the proven
// winner), weight-form bilinear (4 FMA/ch, depth-1), reg cap for 10 CTAs/SM,
// streaming stores so the 50MB output doesn't evict the L2-resident pyramid.
// grid = (N, PH); block = 64 (thread = channel-group of 4).
// ---------------------------------------------------------------------------
__global__ void __launch_bounds__(64, 10)
roi_align_kernel(const float* __restrict__ f0,
                 const float* __restrict__ f1,
                 const float* __restrict__ f2,
                 const float* __restrict__ f3,
                 float* __restrict__ out) {
    int roi = blockIdx.x;
    int py  = blockIdx.y;
    int c4  = threadIdx.x;   // 0..63

    float4 cb = g_scoord[roi];
    int lvl = g_slvl[roi];

    const float* f = (lvl == 0) ? f0 : (lvl == 1) ? f1 : (lvl == 2) ? f2 : f3;
    int W = 256 >> lvl;
    float Wm1 = (float)(W - 1);

    float iy = cb.x + (float)py * cb.y;
    float y0f = floorf(iy);
    float ly = iy - y0f;
    int y0 = min(max((int)y0f, 0), W - 1);
    int y1 = min(max((int)y0f + 1, 0), W - 1);
    bool vy = (iy >= 0.0f) && (iy <= Wm1);
    float omly = 1.0f - ly;

    const float4* f4p = (const float4*)f;
    const float4* row0 = f4p + (size_t)y0 * W * C4 + c4;
    const float4* row1 = f4p + (size_t)y1 * W * C4 + c4;
    float4* o = (float4*)out + ((size_t)(roi * PH + py) * PW) * C4 + c4;

#pragma unroll
    for (int px = 0; px < PW; px++) {
        float ix = cb.z + (float)px * cb.w;
        float x0f = floorf(ix);
        float lx = ix - x0f;
        int x0 = min(max((int)x0f, 0), W - 1);
        int x1 = min(max((int)x0f + 1, 0), W - 1);
        bool vx = (ix >= 0.0f) && (ix <= Wm1);

        float4 f00 = __ldg(row0 + x0 * C4);
        float4 f01 = __ldg(row0 + x1 * C4);
        float4 f10 = __ldg(row1 + x0 * C4);
        float4 f11 = __ldg(row1 + x1 * C4);

        float omlx = 1.0f - lx;
        float w00 = omlx * omly;
        float w01 = lx * omly;
        float w10 = omlx * ly;
        float w11 = lx * ly;

        float4 r;
        r.x = fmaf(f11.x, w11, fmaf(f10.x, w10, fmaf(f01.x, w01, f00.x * w00)));
        r.y = fmaf(f11.y, w11, fmaf(f10.y, w10, fmaf(f01.y, w01, f00.y * w00)));
        r.z = fmaf(f11.z, w11, fmaf(f10.z, w10, fmaf(f01.z, w01, f00.z * w00)));
        r.w = fmaf(f11.w, w11, fmaf(f10.w, w10, fmaf(f01.w, w01, f00.w * w00)));

        if (!(vy && vx)) r = make_float4(0.f, 0.f, 0.f, 0.f);
        __stcs(o + px * C4, r);
    }
}

extern "C" void kernel_launch(void* const* d_in, const int* in_sizes, int n_in,
                              void* d_out, int out_size) {
    const float* f0   = (const float*)d_in[0];
    const float* f1   = (const float*)d_in[1];
    const float* f2   = (const float*)d_in[2];
    const float* f3   = (const float*)d_in[3];
    const float* rois = (const float*)d_in[4];
    float* out = (float*)d_out;

    int N = in_sizes[4] / 4;
    if (N > MAXN) N = MAXN;

    level_sort_kernel<<<1, 1024>>>(rois, N);

    dim3 grid(N, PH);
    roi_align_kernel<<<grid, 64>>>(f0, f1, f2, f3, out);
}